// round 14
// baseline (speedup 1.0000x reference)
#include <cuda_runtime.h>
#include <cuda_bf16.h>
#include <math.h>
#include <stdint.h>

// ---------------- problem constants ----------------
#define BB   2
#define SS   8192
#define DD   1024
#define HH   16
#define GG   128

typedef __nv_bfloat16 bf16;
typedef __nv_bfloat162 bf162;

// ---------------- bf16 chunk-interleaved GEMM operands ----------------
// row layout: 32 chunks x 128B; chunk c = [hi of cols c*32..c*32+31 | lo of same]
__device__ bf16 d_Q2 [(size_t)16384*2048];
__device__ bf16 d_K2 [(size_t)16384*2048];
__device__ bf16 d_V2 [(size_t)16384*2048];
__device__ bf16 d_G2 [(size_t)256*2048];
__device__ bf16 d_C2 [(size_t)16384*2048];   // attention ctx (local)
__device__ bf16 d_Cg2[(size_t)256*2048];     // attention ctx (global)
__device__ bf16 d_Wq2[(size_t)1024*2048];
__device__ bf16 d_Wk2[(size_t)1024*2048];
__device__ bf16 d_Wv2[(size_t)1024*2048];
__device__ bf16 d_Wo2[(size_t)1024*2048];

// head-split projected tensors, bf16, row = token, 128 cols = [hi(64)|lo(64)]
__device__ bf16 d_lq2[(size_t)BB*HH*SS*128];
__device__ bf16 d_lk2[(size_t)BB*HH*SS*128];
__device__ bf16 d_lv2[(size_t)BB*HH*SS*128];
__device__ bf16 d_gq2[(size_t)BB*HH*GG*128];
__device__ bf16 d_gk2[(size_t)BB*HH*GG*128];
__device__ bf16 d_gv2[(size_t)BB*HH*GG*128];

// ---------------- helpers ----------------
__device__ __forceinline__ uint32_t smem_u32(const void* p) {
    uint32_t a;
    asm("{ .reg .u64 t; cvta.to.shared.u64 t, %1; cvt.u32.u64 %0, t; }"
        : "=r"(a) : "l"(p));
    return a;
}
__device__ __forceinline__ void ldsm_x4(uint32_t* r, uint32_t addr) {
    asm volatile("ldmatrix.sync.aligned.m8n8.x4.shared.b16 {%0,%1,%2,%3}, [%4];"
                 : "=r"(r[0]), "=r"(r[1]), "=r"(r[2]), "=r"(r[3]) : "r"(addr));
}
__device__ __forceinline__ void ldsm_x4_t(uint32_t* r, uint32_t addr) {
    asm volatile("ldmatrix.sync.aligned.m8n8.x4.trans.shared.b16 {%0,%1,%2,%3}, [%4];"
                 : "=r"(r[0]), "=r"(r[1]), "=r"(r[2]), "=r"(r[3]) : "r"(addr));
}
__device__ __forceinline__ void mma_bf16(float* d, const uint32_t* a, const uint32_t* b) {
    asm volatile("mma.sync.aligned.m16n8k16.row.col.f32.bf16.bf16.f32 "
                 "{%0,%1,%2,%3}, {%4,%5,%6,%7}, {%8,%9}, {%0,%1,%2,%3};"
                 : "+f"(d[0]), "+f"(d[1]), "+f"(d[2]), "+f"(d[3])
                 : "r"(a[0]), "r"(a[1]), "r"(a[2]), "r"(a[3]),
                   "r"(b[0]), "r"(b[1]));
}
__device__ __forceinline__ uint32_t pack_hi(float x, float y) {
    bf162 t = __halves2bfloat162(__float2bfloat16(x), __float2bfloat16(y));
    return *(uint32_t*)&t;
}
__device__ __forceinline__ uint32_t pack_lo(float x, float y) {
    bf16 hx = __float2bfloat16(x), hy = __float2bfloat16(y);
    bf162 t = __halves2bfloat162(__float2bfloat16(x - __bfloat162float(hx)),
                                 __float2bfloat16(y - __bfloat162float(hy)));
    return *(uint32_t*)&t;
}

// ============================================================================
// conv_all: fp32 [M,1024] -> bf16 [M,2048] chunk-interleaved (R9 exact).
// ============================================================================
__global__ void conv_all(const float* __restrict__ Q,  const float* __restrict__ K,
                         const float* __restrict__ V,  const float* __restrict__ Gt,
                         const float* __restrict__ Wq, const float* __restrict__ Wk,
                         const float* __restrict__ Wv, const float* __restrict__ Wo,
                         bf16* __restrict__ Q2, bf16* __restrict__ K2,
                         bf16* __restrict__ V2, bf16* __restrict__ G2,
                         bf16* __restrict__ Wq2, bf16* __restrict__ Wk2,
                         bf16* __restrict__ Wv2, bf16* __restrict__ Wo2)
{
    int bx = blockIdx.x;
    const float* X; bf16* Y; size_t row;
    if (bx < 4096) {
        int z = bx >> 10; row = bx & 1023;
        X = (z==0)?Wq:(z==1)?Wk:(z==2)?Wv:Wo;
        Y = (z==0)?Wq2:(z==1)?Wk2:(z==2)?Wv2:Wo2;
    } else if (bx < 53248) {
        int i = bx - 4096; int z = i >> 14; row = i & 16383;
        X = (z==0)?Q:(z==1)?K:V;
        Y = (z==0)?Q2:(z==1)?K2:V2;
    } else {
        row = bx - 53248; X = Gt; Y = G2;
    }
    int col = threadIdx.x * 4;
    float4 x = *(const float4*)(X + row*1024 + col);
    bf16 h0 = __float2bfloat16(x.x), h1 = __float2bfloat16(x.y);
    bf16 h2 = __float2bfloat16(x.z), h3 = __float2bfloat16(x.w);
    const int c = col >> 5;
    const int p = col & 31;
    bf16* base = Y + row*2048 + c*64 + p;
    bf162* ph = (bf162*)base;
    bf162* pl = (bf162*)(base + 32);
    ph[0] = __halves2bfloat162(h0, h1);
    ph[1] = __halves2bfloat162(h2, h3);
    pl[0] = __halves2bfloat162(__float2bfloat16(x.x - __bfloat162float(h0)),
                               __float2bfloat16(x.y - __bfloat162float(h1)));
    pl[1] = __halves2bfloat162(__float2bfloat16(x.z - __bfloat162float(h2)),
                               __float2bfloat16(x.w - __bfloat162float(h3)));
}

// ============================================================================
// gemm_tc: merged-chunk bf16x3 on mma.sync, chunk-interleaved operands.
// ROUND 14: PERSISTENT TILES. Each CTA runs one continuous 3-stage pipeline
// over ntiles*32 virtual chunks (tile = blockIdx.x + k*gridDim.x, flattened
// (z, m, n) with n fastest). Epilogue fires at each 32-chunk boundary while
// the next tile's chunks are already in flight — no per-tile warm-up, no
// wave-quantization tail.
// ============================================================================
#define NST  3
#define STB  32768
#define GEMM_SMEM (NST*STB)

__global__ void __launch_bounds__(256, 2) gemm_tc(
    const bf16* __restrict__ A0, const bf16* __restrict__ A1,
    const bf16* __restrict__ A2, const bf16* __restrict__ Ag,
    const bf16* __restrict__ W0, const bf16* __restrict__ W1,
    const bf16* __restrict__ W2,
    const float* __restrict__ Bi0, const float* __restrict__ Bi1,
    const float* __restrict__ Bi2,
    int nbig, int mode, int ntiles, float* __restrict__ outp)
{
    extern __shared__ char smem[];
    const uint32_t sb  = smem_u32(smem);
    const int tid  = threadIdx.x;
    const int wid  = tid >> 5;
    const int lane = tid & 31;
    const int NCTA = gridDim.x;

    const int mytiles = (ntiles - (int)blockIdx.x + NCTA - 1) / NCTA;
    if (mytiles <= 0) return;
    const int total = mytiles * 32;

    const int      r0  = tid >> 3;
    const int      c16 = tid & 7;
    const uint32_t swo = (uint32_t)(tid*16) ^ ((uint32_t)(tid*2) & 0x70);

    // tile params from local tile index
    auto tileinfo = [&](int lt, int& z, int& m0, int& n0, bool& big) {
        int tau = (int)blockIdx.x + lt * NCTA;
        int rem;
        if (mode == 0) { z = tau / 1040; rem = tau - z * 1040; }
        else           { z = 0;          rem = tau; }
        int bm = rem >> 3;
        n0 = (rem & 7) * 128;
        big = bm < nbig;
        m0 = (big ? bm : bm - nbig) * 128;
    };

    auto load_stage = [&](int stage, int vc) {
        const int lt = vc >> 5, c = vc & 31;
        int z, m0, n0; bool big;
        tileinfo(lt, z, m0, n0, big);
        const bf16* A = big ? ((z==0)?A0:(z==1)?A1:A2) : Ag;
        const bf16* W = (z==0)?W0:(z==1)?W1:W2;
        const bf16* ga = A + (size_t)(m0 + r0)*2048 + c16*8 + c*64;
        const bf16* gw = W + (size_t)(n0 + r0)*2048 + c16*8 + c*64;
        const uint32_t smA = sb + stage*STB;
        const uint32_t smB = smA + 16384;
#pragma unroll
        for (int i = 0; i < 4; ++i)
            asm volatile("cp.async.cg.shared.global [%0], [%1], 16;"
                         :: "r"(smA + swo + i*4096), "l"(ga + (size_t)i*32*2048));
#pragma unroll
        for (int i = 0; i < 4; ++i)
            asm volatile("cp.async.cg.shared.global [%0], [%1], 16;"
                         :: "r"(smB + swo + i*4096), "l"(gw + (size_t)i*32*2048));
        asm volatile("cp.async.commit_group;" ::: "memory");
    };

    const int wr = wid & 3;
    const int wc = wid >> 2;
    const int arow = wr*32 + (lane & 15);
    const int akb  = lane >> 4;
    const int g    = lane >> 3;
    const int brow = wc*64 + (g >> 1)*8 + (lane & 7);
    const int bkb  = g & 1;

    float acc[2][8][4];
#pragma unroll
    for (int t = 0; t < 2; ++t)
#pragma unroll
        for (int j = 0; j < 8; ++j)
#pragma unroll
            for (int e = 0; e < 4; ++e) acc[t][j][e] = 0.f;

    load_stage(0, 0);
    load_stage(1, 1);

    for (int vc = 0; vc < total; ++vc) {
        if (vc < total-1) asm volatile("cp.async.wait_group 1;" ::: "memory");
        else              asm volatile("cp.async.wait_group 0;" ::: "memory");
        __syncthreads();
        if (vc + 2 < total) load_stage((vc+2) % NST, vc+2);

        const uint32_t smA = sb + (vc % NST)*STB;
        const uint32_t smB = smA + 16384;

#pragma unroll
        for (int ks = 0; ks < 2; ++ks) {
            uint32_t ah[2][4], al[2][4], bmat[4][4];
#pragma unroll
            for (int t = 0; t < 2; ++t) {
                int row = arow + t*16;
                uint32_t off = (uint32_t)(((ks*2 + akb)*16) ^ ((row & 7)*16));
                ldsm_x4(ah[t], smA + row*128 + off);
            }
#pragma unroll
            for (int t = 0; t < 2; ++t) {
                int row = arow + t*16;
                uint32_t off = (uint32_t)((((4 + ks*2 + akb)*16)) ^ ((row & 7)*16));
                ldsm_x4(al[t], smA + row*128 + off);
            }
#pragma unroll
            for (int u = 0; u < 4; ++u) {
                int row = brow + u*16;
                uint32_t off = (uint32_t)(((ks*2 + bkb)*16) ^ ((row & 7)*16));
                ldsm_x4(bmat[u], smB + row*128 + off);
            }
#pragma unroll
            for (int t = 0; t < 2; ++t)
#pragma unroll
                for (int j = 0; j < 8; ++j)
                    mma_bf16(acc[t][j], ah[t], &bmat[j>>1][(j&1)*2]);
#pragma unroll
            for (int t = 0; t < 2; ++t)
#pragma unroll
                for (int j = 0; j < 8; ++j)
                    mma_bf16(acc[t][j], al[t], &bmat[j>>1][(j&1)*2]);
#pragma unroll
            for (int u = 0; u < 4; ++u) {
                int row = brow + u*16;
                uint32_t off = (uint32_t)((((4 + ks*2 + bkb)*16)) ^ ((row & 7)*16));
                ldsm_x4(bmat[u], smB + row*128 + off);
            }
#pragma unroll
            for (int t = 0; t < 2; ++t)
#pragma unroll
                for (int j = 0; j < 8; ++j)
                    mma_bf16(acc[t][j], ah[t], &bmat[j>>1][(j&1)*2]);
        }

        // ---- tile boundary: epilogue (regs/global only; smem-safe) ----
        if ((vc & 31) == 31) {
            int z, m0, n0; bool big;
            tileinfo(vc >> 5, z, m0, n0, big);
            const float* bias = (z==0)?Bi0:(z==1)?Bi1:Bi2;
            const float scale = (mode == 0 && z == 0) ? 0.125f : 1.0f;
#pragma unroll
            for (int t = 0; t < 2; ++t) {
                const int r1 = m0 + wr*32 + t*16 + (lane >> 2);
                const int r2 = r1 + 8;
#pragma unroll
                for (int j = 0; j < 8; ++j) {
                    const int nb = n0 + wc*64 + j*8 + (lane & 3)*2;
                    float2 bv = *(const float2*)(bias + nb);
                    float2 v1, v2;
                    v1.x = (acc[t][j][0] + bv.x) * scale;
                    v1.y = (acc[t][j][1] + bv.y) * scale;
                    v2.x = (acc[t][j][2] + bv.x) * scale;
                    v2.y = (acc[t][j][3] + bv.y) * scale;
                    if (mode == 2) {
                        const size_t ro = big ? 0 : 16384;
                        *(float2*)(outp + (ro + r1) * 1024 + nb) = v1;
                        *(float2*)(outp + (ro + r2) * 1024 + nb) = v2;
                    } else {
                        bf16* T = big ? ((z==0)?d_lq2:(z==1)?d_lk2:d_lv2)
                                      : ((z==0)?d_gq2:(z==1)?d_gk2:d_gv2);
                        const int Lr = big ? SS : GG;
                        const int h = nb >> 6;
                        const int f = nb & 63;
                        {
                            int b = r1 / Lr, s = r1 - b*Lr;
                            bf16* base = T + ((size_t)(b*HH + h)*Lr + s)*128 + f;
                            *(uint32_t*)base        = pack_hi(v1.x, v1.y);
                            *(uint32_t*)(base + 64) = pack_lo(v1.x, v1.y);
                        }
                        {
                            int b = r2 / Lr, s = r2 - b*Lr;
                            bf16* base = T + ((size_t)(b*HH + h)*Lr + s)*128 + f;
                            *(uint32_t*)base        = pack_hi(v2.x, v2.y);
                            *(uint32_t*)(base + 64) = pack_lo(v2.x, v2.y);
                        }
                    }
                    acc[t][j][0] = 0.f; acc[t][j][1] = 0.f;
                    acc[t][j][2] = 0.f; acc[t][j][3] = 0.f;
                }
            }
        }
    }
}

// ============================================================================
// attn_tc: flash attention on tensor cores (bf16x3), merged launch, 256 thr,
// 2 CTAs/SM (Round-9 proven, unchanged).
// ============================================================================
#define ASTB 32768
#define ATT_SMEM (3*ASTB)
#define NGLOB 64

__global__ void __launch_bounds__(256, 2) attn_tc(const float* __restrict__ mask)
{
    extern __shared__ char smem[];
    const uint32_t sb = smem_u32(smem);
    const int tid  = threadIdx.x;
    const int lane = tid & 31;
    const int w    = tid >> 5;

    const bf16 *qb, *kg, *vg, *kl, *vl;
    const float* mrow;
    bf16* outC;
    size_t outrow0;
    float ps;
    int nch, nact, qtiles;

    if (blockIdx.x < NGLOB) {
        int bi = blockIdx.x;
        int qt = bi & 1;  bi >>= 1;
        int h  = bi & 15;
        int b  = bi >> 4;
        size_t bh = (size_t)(b*HH + h);
        qb = d_gq2 + (bh*GG + qt*64)*128;
        kg = d_gk2 + bh*GG*128;
        vg = d_gv2 + bh*GG*128;
        kl = d_lk2 + bh*SS*128;
        vl = d_lv2 + bh*SS*128;
        mrow = mask + b*SS;
        outC = d_Cg2 + (size_t)(h*128);
        outrow0 = (size_t)b*GG + qt*64;
        ps = 0.125f; nch = 130; nact = 128; qtiles = 1;
    } else {
        int bi = blockIdx.x - NGLOB;
        int qt = bi & 3;  bi >>= 2;
        int n  = bi & 15; bi >>= 4;
        int h  = bi & 15;
        int b  = bi >> 4;
        size_t bh = (size_t)(b*HH + h);
        qb = d_lq2 + (bh*SS + n*512 + qt*128)*128;
        kg = d_gk2 + bh*GG*128;
        vg = d_gv2 + bh*GG*128;
        kl = d_lk2 + (bh*SS + n*512)*128;
        vl = d_lv2 + (bh*SS + n*512)*128;
        mrow = mask + b*SS + n*512;
        outC = d_C2 + (size_t)(h*128);
        outrow0 = (size_t)b*SS + n*512 + qt*128;
        ps = 1.0f; nch = 10; nact = 256; qtiles = 2;
    }

    // ---- stage Q ----
    {
        const int nu = qtiles * 1024;
        for (int u = tid; u < nu; u += 256) {
            int t = u >> 10;
            int v = u & 1023;
            uint32_t sw = (uint32_t)((v*16) ^ (((v>>3)&7)*16));
            const bf16* s = qb + (size_t)(t*64 + ((v>>3)&63))*128 + (v>>9)*64 + (v&7)*8;
            asm volatile("cp.async.cg.shared.global [%0], [%1], 16;"
                         :: "r"(sb + t*ASTB + sw), "l"(s));
        }
        asm volatile("cp.async.commit_group;" ::: "memory");
        asm volatile("cp.async.wait_group 0;" ::: "memory");
        __syncthreads();
    }
    uint32_t qh[4][4], ql[4][4];
    if (w < qtiles*4) {
        const uint32_t tb = sb + (w>>2)*ASTB;
        const int arow = (w&3)*16 + (lane & 15);
        const int akb  = lane >> 4;
#pragma unroll
        for (int ks = 0; ks < 4; ++ks) {
            uint32_t off = (uint32_t)((ks*2 + akb)*16);
            ldsm_x4(qh[ks], tb + arow*128 + (off ^ ((arow & 7)*16)));
            int arl = arow + 64;
            ldsm_x4(ql[ks], tb + arl*128  + (off ^ ((arl & 7)*16)));
        }
    }
    __syncthreads();
    if (w >= qtiles*4) return;

    auto load_chunk = [&](int c, int stage) {
        const bf16 *ksrc, *vsrc;
        if (c < 2) { ksrc = kg + (size_t)c*8192;     vsrc = vg + (size_t)c*8192; }
        else       { ksrc = kl + (size_t)(c-2)*8192; vsrc = vl + (size_t)(c-2)*8192; }
        const uint32_t dK = sb + stage*ASTB;
        const uint32_t dV = dK + 16384;
        for (int u = tid; u < 1024; u += nact) {
            uint32_t sw = (uint32_t)((u*16) ^ (((u>>3)&7)*16));
            size_t so = (size_t)((u>>3)&63)*128 + (u>>9)*64 + (u&7)*8;
            asm volatile("cp.async.cg.shared.global [%0], [%1], 16;"
                         :: "r"(dK + sw), "l"(ksrc + so));
            asm volatile("cp.async.cg.shared.global [%0], [%1], 16;"
                         :: "r"(dV + sw), "l"(vsrc + so));
        }
        asm volatile("cp.async.commit_group;" ::: "memory");
    };

    load_chunk(0, 0);
    load_chunk(1, 1);

    float m0r = -1e30f, m1r = -1e30f, l0r = 0.f, l1r = 0.f;
    float oacc[8][4];
#pragma unroll
    for (int j = 0; j < 8; ++j)
#pragma unroll
        for (int e = 0; e < 4; ++e) oacc[j][e] = 0.f;

    const int g     = lane >> 3;
    const int brow0 = (g >> 1)*8 + (lane & 7);
    const int bkb   = g & 1;
    const int vrow0 = (g & 1)*8 + (lane & 7);
    const int vcol  = (g >> 1)*16;

    for (int c = 0; c < nch; ++c) {
        if (c < nch-1) asm volatile("cp.async.wait_group 1;" ::: "memory");
        else           asm volatile("cp.async.wait_group 0;" ::: "memory");
        __syncthreads();
        if (c + 2 < nch) load_chunk(c+2, (c+2) % 3);

        const uint32_t Kb = sb + (c % 3)*ASTB;
        const uint32_t Vb = Kb + 16384;

        // ---- scores (Qhi.Khi + Qlo.Khi + Qhi.Klo) ----
        float sacc[8][4];
#pragma unroll
        for (int j = 0; j < 8; ++j)
#pragma unroll
            for (int e = 0; e < 4; ++e) sacc[j][e] = 0.f;

#pragma unroll
        for (int ks = 0; ks < 4; ++ks) {
            uint32_t bfh[4][4];
#pragma unroll
            for (int u = 0; u < 4; ++u) {
                int row = brow0 + u*16;
                uint32_t off = (uint32_t)((ks*2 + bkb)*16);
                ldsm_x4(bfh[u], Kb + row*128 + (off ^ ((row & 7)*16)));
            }
#pragma unroll
            for (int j = 0; j < 8; ++j) {
                mma_bf16(sacc[j], qh[ks], &bfh[j>>1][(j&1)*2]);
                mma_bf16(sacc[j], ql[ks], &bfh[j>>1][(j&1)*2]);
            }
            uint32_t bfl[4][4];
#pragma unroll
            for (int u = 0; u < 4; ++u) {
                int row = brow0 + u*16 + 64;
                uint32_t off = (uint32_t)((ks*2 + bkb)*16);
                ldsm_x4(bfl[u], Kb + row*128 + (off ^ ((row & 7)*16)));
            }
#pragma unroll
            for (int j = 0; j < 8; ++j)
                mma_bf16(sacc[j], qh[ks], &bfl[j>>1][(j&1)*2]);
        }

        // ---- mask + online softmax ----
        float mx0 = -1e30f, mx1 = -1e30f;
        const int kb0 = (c - 2)*64 + (lane & 3)*2;
#pragma unroll
        for (int j = 0; j < 8; ++j) {
            float mkx = 0.f, mky = 0.f;
            if (c >= 2) {
                float2 mm = __ldg((const float2*)(mrow + kb0 + j*8));
                mkx = mm.x; mky = mm.y;
            }
            sacc[j][0] = fmaf(sacc[j][0], ps, mkx);
            sacc[j][1] = fmaf(sacc[j][1], ps, mky);
            sacc[j][2] = fmaf(sacc[j][2], ps, mkx);
            sacc[j][3] = fmaf(sacc[j][3], ps, mky);
            mx0 = fmaxf(mx0, fmaxf(sacc[j][0], sacc[j][1]));
            mx1 = fmaxf(mx1, fmaxf(sacc[j][2], sacc[j][3]));
        }
        mx0 = fmaxf(mx0, __shfl_xor_sync(0xffffffffu, mx0, 1));
        mx0 = fmaxf(mx0, __shfl_xor_sync(0xffffffffu, mx0, 2));
        mx1 = fmaxf(mx1, __shfl_xor_sync(0xffffffffu, mx1, 1));
        mx1 = fmaxf(mx1, __shfl_xor_sync(0xffffffffu, mx1, 2));

        float mn0 = fmaxf(m0r, mx0), mn1 = fmaxf(m1r, mx1);
        float a0 = __expf(m0r - mn0), a1 = __expf(m1r - mn1);
        m0r = mn0; m1r = mn1;

        float sum0 = 0.f, sum1 = 0.f;
#pragma unroll
        for (int j = 0; j < 8; ++j) {
            sacc[j][0] = __expf(sacc[j][0] - mn0);
            sacc[j][1] = __expf(sacc[j][1] - mn0);
            sacc[j][2] = __expf(sacc[j][2] - mn1);
            sacc[j][3] = __expf(sacc[j][3] - mn1);
            sum0 += sacc[j][0] + sacc[j][1];
            sum1 += sacc[j][2] + sacc[j][3];
        }
        sum0 += __shfl_xor_sync(0xffffffffu, sum0, 1);
        sum0 += __shfl_xor_sync(0xffffffffu, sum0, 2);
        sum1 += __shfl_xor_sync(0xffffffffu, sum1, 1);
        sum1 += __shfl_xor_sync(0xffffffffu, sum1, 2);
        l0r = l0r*a0 + sum0;
        l1r = l1r*a1 + sum1;
#pragma unroll
        for (int j = 0; j < 8; ++j) {
            oacc[j][0] *= a0; oacc[j][1] *= a0;
            oacc[j][2] *= a1; oacc[j][3] *= a1;
        }

        // ---- P fragments (register-local hi/lo split) + PV ----
#pragma unroll
        for (int kv = 0; kv < 4; ++kv) {
            uint32_t pah[4], pal[4];
            pah[0] = pack_hi(sacc[2*kv][0],   sacc[2*kv][1]);
            pah[1] = pack_hi(sacc[2*kv][2],   sacc[2*kv][3]);
            pah[2] = pack_hi(sacc[2*kv+1][0], sacc[2*kv+1][1]);
            pah[3] = pack_hi(sacc[2*kv+1][2], sacc[2*kv+1][3]);
            pal[0] = pack_lo(sacc[2*kv][0],   sacc[2*kv][1]);
            pal[1] = pack_lo(sacc[2*kv][2],   sacc[2*kv][3]);
            pal[2] = pack_lo(sacc[2*kv+1][0], sacc[2*kv+1][1]);
            pal[3] = pack_lo(sacc[2*kv+1][2], sacc[2*kv+1][3]);

            uint32_t vfh[4][4];
#pragma unroll
            for (int dg = 0; dg < 4; ++dg) {
                int row = kv*16 + vrow0;
                uint32_t off = (uint32_t)(dg*32 + vcol);
                ldsm_x4_t(vfh[dg], Vb + row*128 + (off ^ ((row & 7)*16)));
            }
#pragma unroll
            for (int j = 0; j < 8; ++j) {
                mma_bf16(oacc[j], pah, &vfh[j>>1][(j&1)*2]);
                mma_bf16(oacc[j], pal, &vfh[j>>1][(j&1)*2]);
            }
            uint32_t vfl[4][4];
#pragma unroll
            for (int dg = 0; dg < 4; ++dg) {
                int row = kv*16 + vrow0 + 64;
                uint32_t off = (uint32_t)(dg*32 + vcol);
                ldsm_x4_t(vfl[dg], Vb + row*128 + (off ^ ((row & 7)*16)));
            }
#pragma unroll
            for (int j = 0; j < 8; ++j)
                mma_bf16(oacc[j], pah, &vfl[j>>1][(j&1)*2]);
        }
    }

    // ---- epilogue: normalize, hi/lo split, write chunk-interleaved ctx ----
    const float inv0 = 1.0f / l0r;
    const float inv1 = 1.0f / l1r;
    const size_t row0 = outrow0 + (w>>2)*64 + (w&3)*16 + (lane >> 2);
    const size_t row1 = row0 + 8;
#pragma unroll
    for (int j = 0; j < 8; ++j) {
        const int col = j*8 + (lane & 3)*2;
        const int co  = (col >> 5)*64 + (col & 31);
        float x0 = oacc[j][0]*inv0, y0 = oacc[j][1]*inv0;
        float x1 = oacc[j][2]*inv1, y1 = oacc[j][3]*inv1;
        bf16* p0 = outC + row0*2048 + co;
        bf16* p1 = outC + row1*2048 + co;
        *(uint32_t*)p0        = pack_hi(x0, y0);
        *(uint32_t*)(p0 + 32) = pack_lo(x0, y0);
        *(uint32_t*)p1        = pack_hi(x1, y1);
        *(uint32_t*)(p1 + 32) = pack_lo(x1, y1);
    }
}

// ============================================================================
extern "C" void kernel_launch(void* const* d_in, const int* in_sizes, int n_in,
                              void* d_out, int out_size) {
    (void)in_sizes; (void)n_in; (void)out_size;
    const float* Q    = (const float*)d_in[0];
    const float* K    = (const float*)d_in[1];
    const float* V    = (const float*)d_in[2];
    const float* Gt   = (const float*)d_in[3];
    const float* mask = (const float*)d_in[4];
    const float* Wq = (const float*)d_in[5];
    const float* bq = (const float*)d_in[6];
    const float* Wk = (const float*)d_in[7];
    const float* bk = (const float*)d_in[8];
    const float* Wv = (const float*)d_in[9];
    const float* bv = (const float*)d_in[10];
    const float* Wo = (const float*)d_in[11];
    const float* bo = (const float*)d_in[12];
    float* out = (float*)d_out;

    void *pQ2, *pK2, *pV2, *pG2, *pC2, *pCg2, *pWq2, *pWk2, *pWv2, *pWo2;
    cudaGetSymbolAddress(&pQ2,  d_Q2);
    cudaGetSymbolAddress(&pK2,  d_K2);
    cudaGetSymbolAddress(&pV2,  d_V2);
    cudaGetSymbolAddress(&pG2,  d_G2);
    cudaGetSymbolAddress(&pC2,  d_C2);
    cudaGetSymbolAddress(&pCg2, d_Cg2);
    cudaGetSymbolAddress(&pWq2, d_Wq2);
    cudaGetSymbolAddress(&pWk2, d_Wk2);
    cudaGetSymbolAddress(&pWv2, d_Wv2);
    cudaGetSymbolAddress(&pWo2, d_Wo2);

    cudaFuncSetAttribute(gemm_tc, cudaFuncAttributeMaxDynamicSharedMemorySize, GEMM_SMEM);
    cudaFuncSetAttribute(attn_tc, cudaFuncAttributeMaxDynamicSharedMemorySize, ATT_SMEM);

    typedef const bf16* bfp;
    typedef bf16* bfpw;

    // all conversions in ONE launch (Round-9 layout)
    conv_all<<<53504, 256>>>(Q, K, V, Gt, Wq, Wk, Wv, Wo,
                             (bfpw)pQ2, (bfpw)pK2, (bfpw)pV2, (bfpw)pG2,
                             (bfpw)pWq2, (bfpw)pWk2, (bfpw)pWv2, (bfpw)pWo2);

    // projections: persistent tiles (3120 tiles over 304 CTAs)
    gemm_tc<<<304, 256, GEMM_SMEM>>>(
        (bfp)pQ2, (bfp)pK2, (bfp)pV2, (bfp)pG2,
        (bfp)pWq2, (bfp)pWk2, (bfp)pWv2,
        bq, bk, bv, 128, 0, 3120, nullptr);

    // attention: merged launch; global long-pole CTAs first
    attn_tc<<<NGLOB + 2048, 256, ATT_SMEM>>>(mask);

    // output projection: persistent tiles (1040 tiles over 304 CTAs)
    gemm_tc<<<304, 256, GEMM_SMEM>>>(
        (bfp)pC2, nullptr, nullptr, (bfp)pCg2,
        (bfp)pWo2, nullptr, nullptr,
        bo, nullptr, nullptr, 128, 2, 1040, out);
}

// round 15
// speedup vs baseline: 1.1182x; 1.1182x over previous
#include <cuda_runtime.h>
#include <cuda_bf16.h>
#include <math.h>
#include <stdint.h>

// ---------------- problem constants ----------------
#define BB   2
#define SS   8192
#define DD   1024
#define HH   16
#define GG   128

typedef __nv_bfloat16 bf16;
typedef __nv_bfloat162 bf162;

// ---------------- bf16 chunk-interleaved GEMM operands ----------------
// row layout: 32 chunks x 128B; chunk c = [hi of cols c*32..c*32+31 | lo of same]
__device__ bf16 d_Q2 [(size_t)16384*2048];
__device__ bf16 d_K2 [(size_t)16384*2048];
__device__ bf16 d_V2 [(size_t)16384*2048];
__device__ bf16 d_G2 [(size_t)256*2048];
__device__ bf16 d_C2 [(size_t)16384*2048];   // attention ctx (local)
__device__ bf16 d_Cg2[(size_t)256*2048];     // attention ctx (global)
__device__ bf16 d_Wq2[(size_t)1024*2048];
__device__ bf16 d_Wk2[(size_t)1024*2048];
__device__ bf16 d_Wv2[(size_t)1024*2048];
__device__ bf16 d_Wo2[(size_t)1024*2048];

// head-split projected tensors, bf16, row = token, 128 cols = [hi(64)|lo(64)]
__device__ bf16 d_lq2[(size_t)BB*HH*SS*128];
__device__ bf16 d_lk2[(size_t)BB*HH*SS*128];
__device__ bf16 d_lv2[(size_t)BB*HH*SS*128];
__device__ bf16 d_gq2[(size_t)BB*HH*GG*128];
__device__ bf16 d_gk2[(size_t)BB*HH*GG*128];
__device__ bf16 d_gv2[(size_t)BB*HH*GG*128];

// ---------------- helpers ----------------
__device__ __forceinline__ uint32_t smem_u32(const void* p) {
    uint32_t a;
    asm("{ .reg .u64 t; cvta.to.shared.u64 t, %1; cvt.u32.u64 %0, t; }"
        : "=r"(a) : "l"(p));
    return a;
}
__device__ __forceinline__ void ldsm_x4(uint32_t* r, uint32_t addr) {
    asm volatile("ldmatrix.sync.aligned.m8n8.x4.shared.b16 {%0,%1,%2,%3}, [%4];"
                 : "=r"(r[0]), "=r"(r[1]), "=r"(r[2]), "=r"(r[3]) : "r"(addr));
}
__device__ __forceinline__ void ldsm_x4_t(uint32_t* r, uint32_t addr) {
    asm volatile("ldmatrix.sync.aligned.m8n8.x4.trans.shared.b16 {%0,%1,%2,%3}, [%4];"
                 : "=r"(r[0]), "=r"(r[1]), "=r"(r[2]), "=r"(r[3]) : "r"(addr));
}
__device__ __forceinline__ void mma_bf16(float* d, const uint32_t* a, const uint32_t* b) {
    asm volatile("mma.sync.aligned.m16n8k16.row.col.f32.bf16.bf16.f32 "
                 "{%0,%1,%2,%3}, {%4,%5,%6,%7}, {%8,%9}, {%0,%1,%2,%3};"
                 : "+f"(d[0]), "+f"(d[1]), "+f"(d[2]), "+f"(d[3])
                 : "r"(a[0]), "r"(a[1]), "r"(a[2]), "r"(a[3]),
                   "r"(b[0]), "r"(b[1]));
}
__device__ __forceinline__ uint32_t pack_hi(float x, float y) {
    bf162 t = __halves2bfloat162(__float2bfloat16(x), __float2bfloat16(y));
    return *(uint32_t*)&t;
}
__device__ __forceinline__ uint32_t pack_lo(float x, float y) {
    bf16 hx = __float2bfloat16(x), hy = __float2bfloat16(y);
    bf162 t = __halves2bfloat162(__float2bfloat16(x - __bfloat162float(hx)),
                                 __float2bfloat16(y - __bfloat162float(hy)));
    return *(uint32_t*)&t;
}

// ============================================================================
// conv_all: fp32 [M,1024] -> bf16 [M,2048] chunk-interleaved (R9 exact:
// 1 row/block, HBM-bound).
// ============================================================================
__global__ void conv_all(const float* __restrict__ Q,  const float* __restrict__ K,
                         const float* __restrict__ V,  const float* __restrict__ Gt,
                         const float* __restrict__ Wq, const float* __restrict__ Wk,
                         const float* __restrict__ Wv, const float* __restrict__ Wo,
                         bf16* __restrict__ Q2, bf16* __restrict__ K2,
                         bf16* __restrict__ V2, bf16* __restrict__ G2,
                         bf16* __restrict__ Wq2, bf16* __restrict__ Wk2,
                         bf16* __restrict__ Wv2, bf16* __restrict__ Wo2)
{
    int bx = blockIdx.x;
    const float* X; bf16* Y; size_t row;
    if (bx < 4096) {
        int z = bx >> 10; row = bx & 1023;
        X = (z==0)?Wq:(z==1)?Wk:(z==2)?Wv:Wo;
        Y = (z==0)?Wq2:(z==1)?Wk2:(z==2)?Wv2:Wo2;
    } else if (bx < 53248) {
        int i = bx - 4096; int z = i >> 14; row = i & 16383;
        X = (z==0)?Q:(z==1)?K:V;
        Y = (z==0)?Q2:(z==1)?K2:V2;
    } else {
        row = bx - 53248; X = Gt; Y = G2;
    }
    int col = threadIdx.x * 4;
    float4 x = *(const float4*)(X + row*1024 + col);
    bf16 h0 = __float2bfloat16(x.x), h1 = __float2bfloat16(x.y);
    bf16 h2 = __float2bfloat16(x.z), h3 = __float2bfloat16(x.w);
    const int c = col >> 5;
    const int p = col & 31;
    bf16* base = Y + row*2048 + c*64 + p;
    bf162* ph = (bf162*)base;
    bf162* pl = (bf162*)(base + 32);
    ph[0] = __halves2bfloat162(h0, h1);
    ph[1] = __halves2bfloat162(h2, h3);
    pl[0] = __halves2bfloat162(__float2bfloat16(x.x - __bfloat162float(h0)),
                               __float2bfloat16(x.y - __bfloat162float(h1)));
    pl[1] = __halves2bfloat162(__float2bfloat16(x.z - __bfloat162float(h2)),
                               __float2bfloat16(x.w - __bfloat162float(h3)));
}

// ============================================================================
// gemm_tc: merged-chunk bf16x3 on mma.sync, chunk-interleaved operands.
// R13 proven config: grid (n=8, m slow) for L2 A-reuse; tensor ~79%,
// DRAM ~6%, regs 128, 2 CTAs/SM.
// ============================================================================
#define NST  3
#define STB  32768
#define NCH  32
#define GEMM_SMEM (NST*STB)

__global__ void __launch_bounds__(256, 2) gemm_tc(
    const bf16* __restrict__ A0, const bf16* __restrict__ A1,
    const bf16* __restrict__ A2, const bf16* __restrict__ Ag,
    const bf16* __restrict__ W0, const bf16* __restrict__ W1,
    const bf16* __restrict__ W2,
    const float* __restrict__ Bi0, const float* __restrict__ Bi1,
    const float* __restrict__ Bi2,
    int nbig, int mode, float* __restrict__ outp)
{
    extern __shared__ char smem[];
    const uint32_t sb  = smem_u32(smem);
    const int tid  = threadIdx.x;
    const int wid  = tid >> 5;
    const int lane = tid & 31;
    const int z    = blockIdx.z;
    const int bm   = blockIdx.y;          // m-block varies slowly
    const bool big = bm < nbig;

    const bf16* A = big ? ((z==0)?A0:(z==1)?A1:A2) : Ag;
    const bf16* W = (z==0)?W0:(z==1)?W1:W2;
    const float* bias = (z==0)?Bi0:(z==1)?Bi1:Bi2;

    const int m0 = (big ? bm : bm - nbig) * 128;
    const int n0 = blockIdx.x * 128;
    const float scale = (mode == 0 && z == 0) ? 0.125f : 1.0f;

    const int      r0  = tid >> 3;
    const int      c16 = tid & 7;
    const uint32_t swo = (uint32_t)(tid*16) ^ ((uint32_t)(tid*2) & 0x70);
    const bf16* Abase = A + (size_t)(m0 + r0)*2048 + c16*8;
    const bf16* Wbase = W + (size_t)(n0 + r0)*2048 + c16*8;

    auto load_stage = [&](int stage, int c) {
        const bf16* ga = Abase + c*64;
        const bf16* gw = Wbase + c*64;
        const uint32_t smA = sb + stage*STB;
        const uint32_t smB = smA + 16384;
#pragma unroll
        for (int i = 0; i < 4; ++i)
            asm volatile("cp.async.cg.shared.global [%0], [%1], 16;"
                         :: "r"(smA + swo + i*4096), "l"(ga + (size_t)i*32*2048));
#pragma unroll
        for (int i = 0; i < 4; ++i)
            asm volatile("cp.async.cg.shared.global [%0], [%1], 16;"
                         :: "r"(smB + swo + i*4096), "l"(gw + (size_t)i*32*2048));
        asm volatile("cp.async.commit_group;" ::: "memory");
    };

    const int wr = wid & 3;
    const int wc = wid >> 2;
    const int arow = wr*32 + (lane & 15);
    const int akb  = lane >> 4;
    const int g    = lane >> 3;
    const int brow = wc*64 + (g >> 1)*8 + (lane & 7);
    const int bkb  = g & 1;

    float acc[2][8][4];
#pragma unroll
    for (int t = 0; t < 2; ++t)
#pragma unroll
        for (int j = 0; j < 8; ++j)
#pragma unroll
            for (int e = 0; e < 4; ++e) acc[t][j][e] = 0.f;

    load_stage(0, 0);
    load_stage(1, 1);

    for (int c = 0; c < NCH; ++c) {
        if (c < NCH-1) asm volatile("cp.async.wait_group 1;" ::: "memory");
        else           asm volatile("cp.async.wait_group 0;" ::: "memory");
        __syncthreads();
        if (c + 2 < NCH) load_stage((c+2) % NST, c+2);

        const uint32_t smA = sb + (c % NST)*STB;
        const uint32_t smB = smA + 16384;

#pragma unroll
        for (int ks = 0; ks < 2; ++ks) {
            uint32_t ah[2][4], al[2][4], bmat[4][4];
#pragma unroll
            for (int t = 0; t < 2; ++t) {
                int row = arow + t*16;
                uint32_t off = (uint32_t)(((ks*2 + akb)*16) ^ ((row & 7)*16));
                ldsm_x4(ah[t], smA + row*128 + off);
            }
#pragma unroll
            for (int t = 0; t < 2; ++t) {
                int row = arow + t*16;
                uint32_t off = (uint32_t)((((4 + ks*2 + akb)*16)) ^ ((row & 7)*16));
                ldsm_x4(al[t], smA + row*128 + off);
            }
#pragma unroll
            for (int u = 0; u < 4; ++u) {
                int row = brow + u*16;
                uint32_t off = (uint32_t)(((ks*2 + bkb)*16) ^ ((row & 7)*16));
                ldsm_x4(bmat[u], smB + row*128 + off);
            }
#pragma unroll
            for (int t = 0; t < 2; ++t)
#pragma unroll
                for (int j = 0; j < 8; ++j)
                    mma_bf16(acc[t][j], ah[t], &bmat[j>>1][(j&1)*2]);
#pragma unroll
            for (int t = 0; t < 2; ++t)
#pragma unroll
                for (int j = 0; j < 8; ++j)
                    mma_bf16(acc[t][j], al[t], &bmat[j>>1][(j&1)*2]);
#pragma unroll
            for (int u = 0; u < 4; ++u) {
                int row = brow + u*16;
                uint32_t off = (uint32_t)((((4 + ks*2 + bkb)*16)) ^ ((row & 7)*16));
                ldsm_x4(bmat[u], smB + row*128 + off);
            }
#pragma unroll
            for (int t = 0; t < 2; ++t)
#pragma unroll
                for (int j = 0; j < 8; ++j)
                    mma_bf16(acc[t][j], ah[t], &bmat[j>>1][(j&1)*2]);
        }
    }
    // no __syncthreads needed: epilogue touches no shared memory

    // ---- epilogue ----
#pragma unroll
    for (int t = 0; t < 2; ++t) {
        const int r1 = m0 + wr*32 + t*16 + (lane >> 2);
        const int r2 = r1 + 8;
#pragma unroll
        for (int j = 0; j < 8; ++j) {
            const int nb = n0 + wc*64 + j*8 + (lane & 3)*2;
            float2 bv = *(const float2*)(bias + nb);
            float2 v1, v2;
            v1.x = (acc[t][j][0] + bv.x) * scale;
            v1.y = (acc[t][j][1] + bv.y) * scale;
            v2.x = (acc[t][j][2] + bv.x) * scale;
            v2.y = (acc[t][j][3] + bv.y) * scale;
            if (mode == 2) {
                const size_t ro = big ? 0 : 16384;
                *(float2*)(outp + (ro + r1) * 1024 + nb) = v1;
                *(float2*)(outp + (ro + r2) * 1024 + nb) = v2;
            } else {
                bf16* T = big ? ((z==0)?d_lq2:(z==1)?d_lk2:d_lv2)
                              : ((z==0)?d_gq2:(z==1)?d_gk2:d_gv2);
                const int Lr = big ? SS : GG;
                const int h = nb >> 6;
                const int f = nb & 63;
                {
                    int b = r1 / Lr, s = r1 - b*Lr;
                    bf16* base = T + ((size_t)(b*HH + h)*Lr + s)*128 + f;
                    *(uint32_t*)base        = pack_hi(v1.x, v1.y);
                    *(uint32_t*)(base + 64) = pack_lo(v1.x, v1.y);
                }
                {
                    int b = r2 / Lr, s = r2 - b*Lr;
                    bf16* base = T + ((size_t)(b*HH + h)*Lr + s)*128 + f;
                    *(uint32_t*)base        = pack_hi(v2.x, v2.y);
                    *(uint32_t*)(base + 64) = pack_lo(v2.x, v2.y);
                }
            }
        }
    }
}

// ============================================================================
// attn_tc: flash attention on tensor cores (bf16x3), merged launch, 256 thr,
// 2 CTAs/SM (Round-9 proven).
// ============================================================================
#define ASTB 32768
#define ATT_SMEM (3*ASTB)
#define NGLOB 64

__global__ void __launch_bounds__(256, 2) attn_tc(const float* __restrict__ mask)
{
    extern __shared__ char smem[];
    const uint32_t sb = smem_u32(smem);
    const int tid  = threadIdx.x;
    const int lane = tid & 31;
    const int w    = tid >> 5;

    const bf16 *qb, *kg, *vg, *kl, *vl;
    const float* mrow;
    bf16* outC;
    size_t outrow0;
    float ps;
    int nch, nact, qtiles;

    if (blockIdx.x < NGLOB) {
        int bi = blockIdx.x;
        int qt = bi & 1;  bi >>= 1;
        int h  = bi & 15;
        int b  = bi >> 4;
        size_t bh = (size_t)(b*HH + h);
        qb = d_gq2 + (bh*GG + qt*64)*128;
        kg = d_gk2 + bh*GG*128;
        vg = d_gv2 + bh*GG*128;
        kl = d_lk2 + bh*SS*128;
        vl = d_lv2 + bh*SS*128;
        mrow = mask + b*SS;
        outC = d_Cg2 + (size_t)(h*128);
        outrow0 = (size_t)b*GG + qt*64;
        ps = 0.125f; nch = 130; nact = 128; qtiles = 1;
    } else {
        int bi = blockIdx.x - NGLOB;
        int qt = bi & 3;  bi >>= 2;
        int n  = bi & 15; bi >>= 4;
        int h  = bi & 15;
        int b  = bi >> 4;
        size_t bh = (size_t)(b*HH + h);
        qb = d_lq2 + (bh*SS + n*512 + qt*128)*128;
        kg = d_gk2 + bh*GG*128;
        vg = d_gv2 + bh*GG*128;
        kl = d_lk2 + (bh*SS + n*512)*128;
        vl = d_lv2 + (bh*SS + n*512)*128;
        mrow = mask + b*SS + n*512;
        outC = d_C2 + (size_t)(h*128);
        outrow0 = (size_t)b*SS + n*512 + qt*128;
        ps = 1.0f; nch = 10; nact = 256; qtiles = 2;
    }

    // ---- stage Q: qtiles x (64 rows, 32KB tile) into stages 0..qtiles-1 ----
    {
        const int nu = qtiles * 1024;
        for (int u = tid; u < nu; u += 256) {
            int t = u >> 10;
            int v = u & 1023;
            uint32_t sw = (uint32_t)((v*16) ^ (((v>>3)&7)*16));
            const bf16* s = qb + (size_t)(t*64 + ((v>>3)&63))*128 + (v>>9)*64 + (v&7)*8;
            asm volatile("cp.async.cg.shared.global [%0], [%1], 16;"
                         :: "r"(sb + t*ASTB + sw), "l"(s));
        }
        asm volatile("cp.async.commit_group;" ::: "memory");
        asm volatile("cp.async.wait_group 0;" ::: "memory");
        __syncthreads();
    }
    uint32_t qh[4][4], ql[4][4];
    if (w < qtiles*4) {
        const uint32_t tb = sb + (w>>2)*ASTB;
        const int arow = (w&3)*16 + (lane & 15);
        const int akb  = lane >> 4;
#pragma unroll
        for (int ks = 0; ks < 4; ++ks) {
            uint32_t off = (uint32_t)((ks*2 + akb)*16);
            ldsm_x4(qh[ks], tb + arow*128 + (off ^ ((arow & 7)*16)));
            int arl = arow + 64;
            ldsm_x4(ql[ks], tb + arl*128  + (off ^ ((arl & 7)*16)));
        }
    }
    __syncthreads();
    if (w >= qtiles*4) return;   // global CTAs: warps 4-7 retire

    auto load_chunk = [&](int c, int stage) {
        const bf16 *ksrc, *vsrc;
        if (c < 2) { ksrc = kg + (size_t)c*8192;     vsrc = vg + (size_t)c*8192; }
        else       { ksrc = kl + (size_t)(c-2)*8192; vsrc = vl + (size_t)(c-2)*8192; }
        const uint32_t dK = sb + stage*ASTB;
        const uint32_t dV = dK + 16384;
        for (int u = tid; u < 1024; u += nact) {
            uint32_t sw = (uint32_t)((u*16) ^ (((u>>3)&7)*16));
            size_t so = (size_t)((u>>3)&63)*128 + (u>>9)*64 + (u&7)*8;
            asm volatile("cp.async.cg.shared.global [%0], [%1], 16;"
                         :: "r"(dK + sw), "l"(ksrc + so));
            asm volatile("cp.async.cg.shared.global [%0], [%1], 16;"
                         :: "r"(dV + sw), "l"(vsrc + so));
        }
        asm volatile("cp.async.commit_group;" ::: "memory");
    };

    load_chunk(0, 0);
    load_chunk(1, 1);

    float m0r = -1e30f, m1r = -1e30f, l0r = 0.f, l1r = 0.f;
    float oacc[8][4];
#pragma unroll
    for (int j = 0; j < 8; ++j)
#pragma unroll
        for (int e = 0; e < 4; ++e) oacc[j][e] = 0.f;

    const int g     = lane >> 3;
    const int brow0 = (g >> 1)*8 + (lane & 7);
    const int bkb   = g & 1;
    const int vrow0 = (g & 1)*8 + (lane & 7);
    const int vcol  = (g >> 1)*16;

    for (int c = 0; c < nch; ++c) {
        if (c < nch-1) asm volatile("cp.async.wait_group 1;" ::: "memory");
        else           asm volatile("cp.async.wait_group 0;" ::: "memory");
        __syncthreads();
        if (c + 2 < nch) load_chunk(c+2, (c+2) % 3);

        const uint32_t Kb = sb + (c % 3)*ASTB;
        const uint32_t Vb = Kb + 16384;

        // ---- scores (Qhi.Khi + Qlo.Khi + Qhi.Klo) ----
        float sacc[8][4];
#pragma unroll
        for (int j = 0; j < 8; ++j)
#pragma unroll
            for (int e = 0; e < 4; ++e) sacc[j][e] = 0.f;

#pragma unroll
        for (int ks = 0; ks < 4; ++ks) {
            uint32_t bfh[4][4];
#pragma unroll
            for (int u = 0; u < 4; ++u) {
                int row = brow0 + u*16;
                uint32_t off = (uint32_t)((ks*2 + bkb)*16);
                ldsm_x4(bfh[u], Kb + row*128 + (off ^ ((row & 7)*16)));
            }
#pragma unroll
            for (int j = 0; j < 8; ++j) {
                mma_bf16(sacc[j], qh[ks], &bfh[j>>1][(j&1)*2]);
                mma_bf16(sacc[j], ql[ks], &bfh[j>>1][(j&1)*2]);
            }
            uint32_t bfl[4][4];
#pragma unroll
            for (int u = 0; u < 4; ++u) {
                int row = brow0 + u*16 + 64;
                uint32_t off = (uint32_t)((ks*2 + bkb)*16);
                ldsm_x4(bfl[u], Kb + row*128 + (off ^ ((row & 7)*16)));
            }
#pragma unroll
            for (int j = 0; j < 8; ++j)
                mma_bf16(sacc[j], qh[ks], &bfl[j>>1][(j&1)*2]);
        }

        // ---- mask + online softmax ----
        float mx0 = -1e30f, mx1 = -1e30f;
        const int kb0 = (c - 2)*64 + (lane & 3)*2;
#pragma unroll
        for (int j = 0; j < 8; ++j) {
            float mkx = 0.f, mky = 0.f;
            if (c >= 2) {
                float2 mm = __ldg((const float2*)(mrow + kb0 + j*8));
                mkx = mm.x; mky = mm.y;
            }
            sacc[j][0] = fmaf(sacc[j][0], ps, mkx);
            sacc[j][1] = fmaf(sacc[j][1], ps, mky);
            sacc[j][2] = fmaf(sacc[j][2], ps, mkx);
            sacc[j][3] = fmaf(sacc[j][3], ps, mky);
            mx0 = fmaxf(mx0, fmaxf(sacc[j][0], sacc[j][1]));
            mx1 = fmaxf(mx1, fmaxf(sacc[j][2], sacc[j][3]));
        }
        mx0 = fmaxf(mx0, __shfl_xor_sync(0xffffffffu, mx0, 1));
        mx0 = fmaxf(mx0, __shfl_xor_sync(0xffffffffu, mx0, 2));
        mx1 = fmaxf(mx1, __shfl_xor_sync(0xffffffffu, mx1, 1));
        mx1 = fmaxf(mx1, __shfl_xor_sync(0xffffffffu, mx1, 2));

        float mn0 = fmaxf(m0r, mx0), mn1 = fmaxf(m1r, mx1);
        float a0 = __expf(m0r - mn0), a1 = __expf(m1r - mn1);
        m0r = mn0; m1r = mn1;

        float sum0 = 0.f, sum1 = 0.f;
#pragma unroll
        for (int j = 0; j < 8; ++j) {
            sacc[j][0] = __expf(sacc[j][0] - mn0);
            sacc[j][1] = __expf(sacc[j][1] - mn0);
            sacc[j][2] = __expf(sacc[j][2] - mn1);
            sacc[j][3] = __expf(sacc[j][3] - mn1);
            sum0 += sacc[j][0] + sacc[j][1];
            sum1 += sacc[j][2] + sacc[j][3];
        }
        sum0 += __shfl_xor_sync(0xffffffffu, sum0, 1);
        sum0 += __shfl_xor_sync(0xffffffffu, sum0, 2);
        sum1 += __shfl_xor_sync(0xffffffffu, sum1, 1);
        sum1 += __shfl_xor_sync(0xffffffffu, sum1, 2);
        l0r = l0r*a0 + sum0;
        l1r = l1r*a1 + sum1;
#pragma unroll
        for (int j = 0; j < 8; ++j) {
            oacc[j][0] *= a0; oacc[j][1] *= a0;
            oacc[j][2] *= a1; oacc[j][3] *= a1;
        }

        // ---- P fragments (register-local hi/lo split) + PV ----
#pragma unroll
        for (int kv = 0; kv < 4; ++kv) {
            uint32_t pah[4], pal[4];
            pah[0] = pack_hi(sacc[2*kv][0],   sacc[2*kv][1]);
            pah[1] = pack_hi(sacc[2*kv][2],   sacc[2*kv][3]);
            pah[2] = pack_hi(sacc[2*kv+1][0], sacc[2*kv+1][1]);
            pah[3] = pack_hi(sacc[2*kv+1][2], sacc[2*kv+1][3]);
            pal[0] = pack_lo(sacc[2*kv][0],   sacc[2*kv][1]);
            pal[1] = pack_lo(sacc[2*kv][2],   sacc[2*kv][3]);
            pal[2] = pack_lo(sacc[2*kv+1][0], sacc[2*kv+1][1]);
            pal[3] = pack_lo(sacc[2*kv+1][2], sacc[2*kv+1][3]);

            uint32_t vfh[4][4];
#pragma unroll
            for (int dg = 0; dg < 4; ++dg) {
                int row = kv*16 + vrow0;
                uint32_t off = (uint32_t)(dg*32 + vcol);
                ldsm_x4_t(vfh[dg], Vb + row*128 + (off ^ ((row & 7)*16)));
            }
#pragma unroll
            for (int j = 0; j < 8; ++j) {
                mma_bf16(oacc[j], pah, &vfh[j>>1][(j&1)*2]);
                mma_bf16(oacc[j], pal, &vfh[j>>1][(j&1)*2]);
            }
            uint32_t vfl[4][4];
#pragma unroll
            for (int dg = 0; dg < 4; ++dg) {
                int row = kv*16 + vrow0 + 64;
                uint32_t off = (uint32_t)(dg*32 + vcol);
                ldsm_x4_t(vfl[dg], Vb + row*128 + (off ^ ((row & 7)*16)));
            }
#pragma unroll
            for (int j = 0; j < 8; ++j)
                mma_bf16(oacc[j], pah, &vfl[j>>1][(j&1)*2]);
        }
    }

    // ---- epilogue: normalize, hi/lo split, write chunk-interleaved ctx ----
    const float inv0 = 1.0f / l0r;
    const float inv1 = 1.0f / l1r;
    const size_t row0 = outrow0 + (w>>2)*64 + (w&3)*16 + (lane >> 2);
    const size_t row1 = row0 + 8;
#pragma unroll
    for (int j = 0; j < 8; ++j) {
        const int col = j*8 + (lane & 3)*2;
        const int co  = (col >> 5)*64 + (col & 31);
        float x0 = oacc[j][0]*inv0, y0 = oacc[j][1]*inv0;
        float x1 = oacc[j][2]*inv1, y1 = oacc[j][3]*inv1;
        bf16* p0 = outC + row0*2048 + co;
        bf16* p1 = outC + row1*2048 + co;
        *(uint32_t*)p0        = pack_hi(x0, y0);
        *(uint32_t*)(p0 + 32) = pack_lo(x0, y0);
        *(uint32_t*)p1        = pack_hi(x1, y1);
        *(uint32_t*)(p1 + 32) = pack_lo(x1, y1);
    }
}

// ============================================================================
extern "C" void kernel_launch(void* const* d_in, const int* in_sizes, int n_in,
                              void* d_out, int out_size) {
    (void)in_sizes; (void)n_in; (void)out_size;
    const float* Q    = (const float*)d_in[0];
    const float* K    = (const float*)d_in[1];
    const float* V    = (const float*)d_in[2];
    const float* Gt   = (const float*)d_in[3];
    const float* mask = (const float*)d_in[4];
    const float* Wq = (const float*)d_in[5];
    const float* bq = (const float*)d_in[6];
    const float* Wk = (const float*)d_in[7];
    const float* bk = (const float*)d_in[8];
    const float* Wv = (const float*)d_in[9];
    const float* bv = (const float*)d_in[10];
    const float* Wo = (const float*)d_in[11];
    const float* bo = (const float*)d_in[12];
    float* out = (float*)d_out;

    void *pQ2, *pK2, *pV2, *pG2, *pC2, *pCg2, *pWq2, *pWk2, *pWv2, *pWo2;
    cudaGetSymbolAddress(&pQ2,  d_Q2);
    cudaGetSymbolAddress(&pK2,  d_K2);
    cudaGetSymbolAddress(&pV2,  d_V2);
    cudaGetSymbolAddress(&pG2,  d_G2);
    cudaGetSymbolAddress(&pC2,  d_C2);
    cudaGetSymbolAddress(&pCg2, d_Cg2);
    cudaGetSymbolAddress(&pWq2, d_Wq2);
    cudaGetSymbolAddress(&pWk2, d_Wk2);
    cudaGetSymbolAddress(&pWv2, d_Wv2);
    cudaGetSymbolAddress(&pWo2, d_Wo2);

    cudaFuncSetAttribute(gemm_tc, cudaFuncAttributeMaxDynamicSharedMemorySize, GEMM_SMEM);
    cudaFuncSetAttribute(attn_tc, cudaFuncAttributeMaxDynamicSharedMemorySize, ATT_SMEM);

    typedef const bf16* bfp;
    typedef bf16* bfpw;

    // all conversions in ONE launch
    conv_all<<<53504, 256>>>(Q, K, V, Gt, Wq, Wk, Wv, Wo,
                             (bfpw)pQ2, (bfpw)pK2, (bfpw)pV2, (bfpw)pG2,
                             (bfpw)pWq2, (bfpw)pWk2, (bfpw)pWv2, (bfpw)pWo2);

    // projections: grid (n=8, m=130, z=3) — m varies slowly for L2 A-reuse
    gemm_tc<<<dim3(8, 130, 3), 256, GEMM_SMEM>>>(
        (bfp)pQ2, (bfp)pK2, (bfp)pV2, (bfp)pG2,
        (bfp)pWq2, (bfp)pWk2, (bfp)pWv2,
        bq, bk, bv, 128, 0, nullptr);

    // attention: merged launch; global long-pole CTAs first
    attn_tc<<<NGLOB + 2048, 256, ATT_SMEM>>>(mask);

    // output projection: grid (8, 130, 1) -> fp32 out
    gemm_tc<<<dim3(8, 130, 1), 256, GEMM_SMEM>>>(
        (bfp)pC2, nullptr, nullptr, (bfp)pCg2,
        (bfp)pWo2, nullptr, nullptr,
        bo, nullptr, nullptr, 128, 2, out);
}